// round 2
// baseline (speedup 1.0000x reference)
#include <cuda_runtime.h>

#define N_NODES 8192
#define DIN 128
#define DOUT 128
#define E_EDGES 262144
#define MWORDS 256          // 8192 bits / 32 per adjacency row
#define MAXD 128            // max unique out-degree (Poisson(32): P(>96) ~ 1e-11)

// ---- scratch (device globals; no allocation allowed) ----
__device__ int      g_deg[N_NODES];
__device__ int      g_cnt[N_NODES];
__device__ unsigned g_mask[N_NODES * MWORDS];      // 8 MB dedup bitmask
__device__ int      g_nbr[N_NODES * MAXD];         // 4 MB neighbor lists
__device__ float    g_feat[N_NODES * DOUT];        // 4 MB: g[j] = dinv[j]*(x[j]W^T + b)
__device__ float    g_wt[DIN * DOUT];              // W^T: g_wt[k*128+c] = W[c][k]

// ------------------------------------------------------- zero scratch + W^T
// Independent work fused into one launch. Grid 512x256 = 131072 threads.
__global__ void k_prep(const float* __restrict__ W) {
    int idx = blockIdx.x * blockDim.x + threadIdx.x;
    int stride = gridDim.x * blockDim.x;
    uint4 z = make_uint4(0, 0, 0, 0);
    const int nm4 = (N_NODES * MWORDS) / 4;
    for (int i = idx; i < nm4; i += stride) ((uint4*)g_mask)[i] = z;
    if (idx < N_NODES) { g_deg[idx] = 0; g_cnt[idx] = 0; }
    if (idx < DIN * DOUT) {                       // transpose W (coalesced write)
        int k = idx / DOUT, c = idx % DOUT;
        g_wt[k * DOUT + c] = W[c * DIN + k];
    }
}

// ---------------------------------------------------------------- edge pass
// deg counts ALL edges (with multiplicity, matching .at[row].add(1.0));
// bitmask dedups adjacency (matching .at[row,col].set -> duplicates count once);
// the FIRST setter of bit (r,c) appends c to r's unique-neighbor list.
__global__ void k_edges(const int* __restrict__ ei) {
    int e = blockIdx.x * blockDim.x + threadIdx.x;
    if (e >= E_EDGES) return;
    int r = ei[e];
    int c = ei[E_EDGES + e];
    atomicAdd(&g_deg[r], 1);
    unsigned m = 1u << (c & 31);
    unsigned old = atomicOr(&g_mask[r * MWORDS + (c >> 5)], m);
    if (!(old & m)) {
        int p = atomicAdd(&g_cnt[r], 1);
        if (p < MAXD) g_nbr[r * MAXD + p] = c;
    }
}

__device__ __forceinline__ float dinv_of(int d) {
    return (d > 0) ? rsqrtf((float)d) : 0.0f;
}

// ---------------------------------------------------------------- fused GEMM
// g_feat[i] = dinv[i] * (x[i] @ W^T + b).  64 rows/block, 256 threads.
// warp w (0..7) owns rows w*8..w*8+7; lane l owns cols 4l..4l+3.
#define GROWS 64
__global__ __launch_bounds__(256) void k_gemm(const float* __restrict__ x,
                                              const float* __restrict__ bias) {
    __shared__ float xs[GROWS][DIN];   // 32 KB
    const int row0 = blockIdx.x * GROWS;
    const int t = threadIdx.x;

    // load x tile: 8192 floats = 256 threads * 8 float4, fully coalesced
    const float4* xin = (const float4*)(x + row0 * DIN);
    float4* xs4 = (float4*)&xs[0][0];
#pragma unroll
    for (int i = 0; i < 8; i++) xs4[t + 256 * i] = xin[t + 256 * i];
    __syncthreads();

    const int w = t >> 5, l = t & 31;
    const int r0 = w * 8;
    const int c0 = l * 4;

    float4 acc[8];
#pragma unroll
    for (int r = 0; r < 8; r++) acc[r] = make_float4(0.f, 0.f, 0.f, 0.f);

#pragma unroll 4
    for (int k = 0; k < DIN; k++) {
        float4 wv = *(const float4*)&g_wt[k * DOUT + c0];   // L1/L2-resident
#pragma unroll
        for (int r = 0; r < 8; r++) {
            float xv = xs[r0 + r][k];                       // warp-uniform broadcast
            acc[r].x += xv * wv.x;
            acc[r].y += xv * wv.y;
            acc[r].z += xv * wv.z;
            acc[r].w += xv * wv.w;
        }
    }

    float4 bv = *(const float4*)&bias[c0];
#pragma unroll
    for (int r = 0; r < 8; r++) {
        int row = row0 + r0 + r;
        float dv = dinv_of(g_deg[row]);
        float4 o;
        o.x = dv * (acc[r].x + bv.x);
        o.y = dv * (acc[r].y + bv.y);
        o.z = dv * (acc[r].z + bv.z);
        o.w = dv * (acc[r].w + bv.w);
        *(float4*)&g_feat[row * DOUT + c0] = o;
    }
}

// ---------------------------------------------------------------- aggregation
// One block per node, thread t = output feature t.
// out[i][t] = relu( dinv[i] * sum_{j in uniq-nbrs(i)} g_feat[j][t] )
__global__ __launch_bounds__(128) void k_agg(float* __restrict__ out) {
    __shared__ int nb[MAXD];
    const int i = blockIdx.x;
    const int t = threadIdx.x;
    int cnt = g_cnt[i];
    if (cnt > MAXD) cnt = MAXD;
    for (int p = t; p < cnt; p += 128) nb[p] = g_nbr[i * MAXD + p];
    __syncthreads();

    float a0 = 0.f, a1 = 0.f, a2 = 0.f, a3 = 0.f;
    int p = 0;
    for (; p + 4 <= cnt; p += 4) {     // 4 independent coalesced L2 gathers in flight
        a0 += g_feat[nb[p + 0] * DOUT + t];
        a1 += g_feat[nb[p + 1] * DOUT + t];
        a2 += g_feat[nb[p + 2] * DOUT + t];
        a3 += g_feat[nb[p + 3] * DOUT + t];
    }
    for (; p < cnt; p++) a0 += g_feat[nb[p] * DOUT + t];

    float v = dinv_of(g_deg[i]) * ((a0 + a1) + (a2 + a3));
    out[i * DOUT + t] = (v > 0.f) ? v : 0.f;
}

// ---------------------------------------------------------------- launch
extern "C" void kernel_launch(void* const* d_in, const int* in_sizes, int n_in,
                              void* d_out, int out_size) {
    const float* x    = (const float*)d_in[0];   // [8192,128] f32
    const int*   ei   = (const int*)d_in[1];     // [2,262144] i32
    const float* W    = (const float*)d_in[2];   // [128,128]  f32
    const float* bias = (const float*)d_in[3];   // [128]      f32
    float* out = (float*)d_out;                  // [8192,128] f32

    k_prep <<<512, 256>>>(W);
    k_edges<<<E_EDGES / 256, 256>>>(ei);
    k_gemm <<<N_NODES / GROWS, 256>>>(x, bias);
    k_agg  <<<N_NODES, 128>>>(out);
}